// round 2
// baseline (speedup 1.0000x reference)
#include <cuda_runtime.h>
#include <cuda_bf16.h>
#include <cstdint>

#define B_ 8
#define N_ 2048
#define D_ 128
#define ALPHA 0.2f

// ---------------- scratch (device globals; no allocations allowed) ----------
__device__ __align__(16) float g_a1W[D_];
__device__ __align__(16) float g_a2W[D_];
__device__ __align__(16) float g_Wh1[B_ * N_];
__device__ __align__(16) float g_Wh2[B_ * N_];
__device__ __align__(16) float g_Sinv[B_ * N_];
__device__ __align__(16) __nv_bfloat16 g_WhT[(size_t)B_ * D_ * N_]; // [b][d][n] bf16, 4MB

// ---------------- K0: aW1[k] = sum_c W[k][c]*a[c],  aW2 with a[d:] ----------
__global__ void k0_wa(const float* __restrict__ W, const float* __restrict__ a) {
    int k = threadIdx.x;
    float s1 = 0.f, s2 = 0.f;
    for (int c = 0; c < D_; c++) {
        float wv = W[k * D_ + c];
        s1 = fmaf(wv, a[c], s1);
        s2 = fmaf(wv, a[D_ + c], s2);
    }
    g_a1W[k] = s1;
    g_a2W[k] = s2;
}

// ---------------- K1b: Wh1[i] = h_i . (W a1), Wh2[i] = h_i . (W a2) --------
// one warp per row
__global__ void k1b_wh12(const float* __restrict__ h) {
    int gw = (blockIdx.x * blockDim.x + threadIdx.x) >> 5;  // global row
    int lane = threadIdx.x & 31;
    float4 hv = *(const float4*)(h + (size_t)gw * D_ + lane * 4);
    float4 a1 = *(const float4*)(g_a1W + lane * 4);
    float4 a2 = *(const float4*)(g_a2W + lane * 4);
    float s1 = hv.x * a1.x + hv.y * a1.y + hv.z * a1.z + hv.w * a1.w;
    float s2 = hv.x * a2.x + hv.y * a2.y + hv.z * a2.z + hv.w * a2.w;
#pragma unroll
    for (int o = 16; o > 0; o >>= 1) {
        s1 += __shfl_down_sync(0xffffffffu, s1, o);
        s2 += __shfl_down_sync(0xffffffffu, s2, o);
    }
    if (lane == 0) {
        g_Wh1[gw] = s1;
        g_Wh2[gw] = s2;
    }
}

// ---------------- K1: Wh = h @ W, stored transposed bf16 [b][d][n] ---------
// block: 128 threads (thread = output column c), 32 rows per block
__global__ void k1_wh(const float* __restrict__ h, const float* __restrict__ W) {
    extern __shared__ float sm[];
    float* s_W = sm;             // [128][128]
    float* s_h = sm + D_ * D_;   // [32][128]
    int c = threadIdx.x;
    int rowbase = blockIdx.x * 32;  // global row
    for (int k = 0; k < D_; k++) s_W[k * D_ + c] = W[k * D_ + c];
    for (int r = 0; r < 32; r++) s_h[r * D_ + c] = h[(size_t)(rowbase + r) * D_ + c];
    __syncthreads();

    float acc[32];
#pragma unroll
    for (int r = 0; r < 32; r++) acc[r] = 0.f;
    for (int k = 0; k < D_; k++) {
        float wv = s_W[k * D_ + c];
#pragma unroll
        for (int r = 0; r < 32; r++) acc[r] = fmaf(s_h[r * D_ + k], wv, acc[r]);
    }
    int b = rowbase >> 11;          // /2048
    int n0 = rowbase & (N_ - 1);
    __nv_bfloat16* dst = g_WhT + ((size_t)(b * D_ + c)) * N_ + n0;
#pragma unroll
    for (int r = 0; r < 32; r += 2) {
        __nv_bfloat162 v = __floats2bfloat162_rn(acc[r], acc[r + 1]);
        *(__nv_bfloat162*)(dst + r) = v;
    }
}

// ---------------- K2: S_i = sum_j adj ? exp(lrelu(Wh1_i + Wh2_j)) : 0 ------
__global__ void k2_rowsum(const int* __restrict__ adj) {
    int row = blockIdx.x;  // 0..16383
    int b = row >> 11;
    const int4* a4 = (const int4*)(adj + (size_t)row * N_);
    const float4* w4 = (const float4*)(g_Wh2 + b * N_);
    float wh1 = g_Wh1[row];
    float s = 0.f;
    for (int j = threadIdx.x; j < N_ / 4; j += 256) {
        int4 m = a4[j];
        float4 v = w4[j];
        float e;
        e = wh1 + v.x; e = fmaxf(e, ALPHA * e); if (m.x) s += __expf(e);
        e = wh1 + v.y; e = fmaxf(e, ALPHA * e); if (m.y) s += __expf(e);
        e = wh1 + v.z; e = fmaxf(e, ALPHA * e); if (m.z) s += __expf(e);
        e = wh1 + v.w; e = fmaxf(e, ALPHA * e); if (m.w) s += __expf(e);
    }
#pragma unroll
    for (int o = 16; o > 0; o >>= 1) s += __shfl_down_sync(0xffffffffu, s, o);
    __shared__ float red[8];
    int lane = threadIdx.x & 31, w = threadIdx.x >> 5;
    if (lane == 0) red[w] = s;
    __syncthreads();
    if (threadIdx.x == 0) {
        float t = 0.f;
#pragma unroll
        for (int i = 0; i < 8; i++) t += red[i];
        g_Sinv[row] = 1.f / t;
    }
}

// ---------------- K3: fused attention write + PV MMA + residual ------------
#define KT 64
#define BSTRIDE (KT + 8)  // bf16 elems per smem B row (padded for LDSM banks)

__device__ __forceinline__ uint32_t packbf2(float x, float y) {
    __nv_bfloat162 v = __floats2bfloat162_rn(x, y);
    return *reinterpret_cast<uint32_t*>(&v);
}

__global__ void __launch_bounds__(256) k3_attn(const int* __restrict__ adj,
                                               const float* __restrict__ h,
                                               float* __restrict__ out,
                                               float* __restrict__ attn) {
    __shared__ __align__(16) __nv_bfloat16 s_B[D_ * BSTRIDE];
    __shared__ float s_w2[KT];
    int tid = threadIdx.x;
    int lane = tid & 31, wrp = tid >> 5;
    int b = blockIdx.y;
    int n0 = blockIdx.x * 128;
    int g = lane >> 2, tg = lane & 3;
    int row_lo = n0 + wrp * 16 + g;
    int gr_lo = b * N_ + row_lo;
    int gr_hi = gr_lo + 8;
    float wh1_lo = g_Wh1[gr_lo], wh1_hi = g_Wh1[gr_hi];
    float si_lo = g_Sinv[gr_lo], si_hi = g_Sinv[gr_hi];
    const int* adj_lo = adj + (size_t)gr_lo * N_;
    const int* adj_hi = adj + (size_t)gr_hi * N_;
    float* at_lo = attn + (size_t)gr_lo * N_;
    float* at_hi = attn + (size_t)gr_hi * N_;
    const __nv_bfloat16* whT = g_WhT + (size_t)b * D_ * N_;

    float acc[16][4];
#pragma unroll
    for (int i = 0; i < 16; i++) { acc[i][0] = acc[i][1] = acc[i][2] = acc[i][3] = 0.f; }

    int mrow = lane & 7;
    int msel = (lane >> 3) & 1;

    for (int jt = 0; jt < N_; jt += KT) {
        __syncthreads();
        {   // cooperative stage: B tile (WhT[d][jt..jt+KT)) + wh2 slice
            int d = tid >> 1, hf = tid & 1;
            const uint4* src = (const uint4*)(whT + (size_t)d * N_ + jt + hf * 32);
            uint4* dst = (uint4*)(s_B + d * BSTRIDE + hf * 32);
            dst[0] = src[0]; dst[1] = src[1]; dst[2] = src[2]; dst[3] = src[3];
            if (tid < KT) s_w2[tid] = g_Wh2[b * N_ + jt + tid];
        }
        __syncthreads();
#pragma unroll
        for (int kk = 0; kk < KT / 16; kk++) {
            int j0 = jt + kk * 16 + tg * 2;
            int2 mlo0 = *(const int2*)(adj_lo + j0);
            int2 mhi0 = *(const int2*)(adj_hi + j0);
            int2 mlo8 = *(const int2*)(adj_lo + j0 + 8);
            int2 mhi8 = *(const int2*)(adj_hi + j0 + 8);
            float2 wa = *(const float2*)(s_w2 + kk * 16 + tg * 2);
            float2 wb = *(const float2*)(s_w2 + kk * 16 + tg * 2 + 8);

            float e, p0, p1, p2, p3, p4, p5, p6, p7;
            e = wh1_lo + wa.x; e = fmaxf(e, ALPHA * e); p0 = mlo0.x ? __expf(e) * si_lo : 0.f;
            e = wh1_lo + wa.y; e = fmaxf(e, ALPHA * e); p1 = mlo0.y ? __expf(e) * si_lo : 0.f;
            e = wh1_hi + wa.x; e = fmaxf(e, ALPHA * e); p2 = mhi0.x ? __expf(e) * si_hi : 0.f;
            e = wh1_hi + wa.y; e = fmaxf(e, ALPHA * e); p3 = mhi0.y ? __expf(e) * si_hi : 0.f;
            e = wh1_lo + wb.x; e = fmaxf(e, ALPHA * e); p4 = mlo8.x ? __expf(e) * si_lo : 0.f;
            e = wh1_lo + wb.y; e = fmaxf(e, ALPHA * e); p5 = mlo8.y ? __expf(e) * si_lo : 0.f;
            e = wh1_hi + wb.x; e = fmaxf(e, ALPHA * e); p6 = mhi8.x ? __expf(e) * si_hi : 0.f;
            e = wh1_hi + wb.y; e = fmaxf(e, ALPHA * e); p7 = mhi8.y ? __expf(e) * si_hi : 0.f;

            *(float2*)(at_lo + j0)     = make_float2(p0, p1);
            *(float2*)(at_hi + j0)     = make_float2(p2, p3);
            *(float2*)(at_lo + j0 + 8) = make_float2(p4, p5);
            *(float2*)(at_hi + j0 + 8) = make_float2(p6, p7);

            uint32_t A0 = packbf2(p0, p1);
            uint32_t A1 = packbf2(p2, p3);
            uint32_t A2 = packbf2(p4, p5);
            uint32_t A3 = packbf2(p6, p7);

            const __nv_bfloat16* bbase = s_B + mrow * BSTRIDE + kk * 16 + msel * 8;
#pragma unroll
            for (int nb = 0; nb < 16; nb++) {
                uint32_t B0, B1;
                uint32_t sa = (uint32_t)__cvta_generic_to_shared(bbase + nb * 8 * BSTRIDE);
                asm volatile("ldmatrix.sync.aligned.m8n8.x2.shared.b16 {%0,%1}, [%2];\n"
                             : "=r"(B0), "=r"(B1) : "r"(sa));
                asm volatile("mma.sync.aligned.m16n8k16.row.col.f32.bf16.bf16.f32 "
                             "{%0,%1,%2,%3}, {%4,%5,%6,%7}, {%8,%9}, {%0,%1,%2,%3};\n"
                             : "+f"(acc[nb][0]), "+f"(acc[nb][1]), "+f"(acc[nb][2]), "+f"(acc[nb][3])
                             : "r"(A0), "r"(A1), "r"(A2), "r"(A3), "r"(B0), "r"(B1));
            }
        }
    }
    // epilogue: out = h + h_prime
#pragma unroll
    for (int nb = 0; nb < 16; nb++) {
        int c = nb * 8 + tg * 2;
        float2 hlo = *(const float2*)(h + (size_t)gr_lo * D_ + c);
        float2 hhi = *(const float2*)(h + (size_t)gr_hi * D_ + c);
        *(float2*)(out + (size_t)gr_lo * D_ + c) = make_float2(hlo.x + acc[nb][0], hlo.y + acc[nb][1]);
        *(float2*)(out + (size_t)gr_hi * D_ + c) = make_float2(hhi.x + acc[nb][2], hhi.y + acc[nb][3]);
    }
}

// ---------------------------------------------------------------------------
extern "C" void kernel_launch(void* const* d_in, const int* in_sizes, int n_in,
                              void* d_out, int out_size) {
    const float* h   = (const float*)d_in[0];
    const int*   adj = (const int*)d_in[1];
    const float* W   = (const float*)d_in[2];
    const float* a   = (const float*)d_in[3];
    float* out  = (float*)d_out;
    float* attn = out + (size_t)B_ * N_ * D_;

    cudaFuncSetAttribute(k1_wh, cudaFuncAttributeMaxDynamicSharedMemorySize, 81920);

    k0_wa<<<1, 128>>>(W, a);
    k1b_wh12<<<(B_ * N_) / 8, 256>>>(h);
    k1_wh<<<(B_ * N_) / 32, 128, 81920>>>(h, W);
    k2_rowsum<<<B_ * N_, 256>>>(adj);
    k3_attn<<<dim3(N_ / 128, B_), 256>>>(adj, h, out, attn);
}